// round 10
// baseline (speedup 1.0000x reference)
#include <cuda_runtime.h>
#include <cuda_bf16.h>
#include <mma.h>
#include <math.h>
#include <stdint.h>

using namespace nvcuda;

// Problem constants
#define T_STEPS 512
#define BATCH   32
#define IDIM    1024
#define HDIM    1024
#define G4      4096                  // 4*H
#define M_TOT   (T_STEPS * BATCH)     // 16384

// ---------------------------------------------------------------------------
// Scratch (static __device__ — no allocation at kernel_launch time)
// ---------------------------------------------------------------------------
__device__ float          g_xg[(size_t)M_TOT * G4];    // 256 MB: precomputed x@W^T
__device__ float          g_xt[(size_t)M_TOT * IDIM];  // 64 MB: x rounded to tf32
__device__ float          g_wt[(size_t)G4 * HDIM];     // 16 MB: W rounded to tf32
__device__ __nv_bfloat16  g_hx[2][BATCH * HDIM];       // h exchange: [hi|lo] planes
__device__ unsigned       g_bar;                        // grid barrier counter

// ---------------------------------------------------------------------------
// cp.async helpers
// ---------------------------------------------------------------------------
__device__ __forceinline__ void cp16(void* dst, const void* src) {
    unsigned d = (unsigned)__cvta_generic_to_shared(dst);
    asm volatile("cp.async.cg.shared.global [%0], [%1], 16;\n" :: "r"(d), "l"(src));
}
__device__ __forceinline__ void cp_commit() { asm volatile("cp.async.commit_group;\n"); }
template <int N>
__device__ __forceinline__ void cp_wait() { asm volatile("cp.async.wait_group %0;\n" :: "n"(N)); }

// ===========================================================================
// Round kernel: x, W -> tf32-rounded fp32 copies (RN), so the GEMM mainloop
// has no conversion math at all.
// ===========================================================================
__global__ __launch_bounds__(256)
void round_kernel(const float* __restrict__ X, const float* __restrict__ W)
{
    const size_t NX4 = (size_t)M_TOT * IDIM / 4;   // 4,194,304
    const size_t NW4 = (size_t)G4 * HDIM / 4;      // 1,048,576
    size_t idx = (size_t)blockIdx.x * blockDim.x + threadIdx.x;
    size_t stride = (size_t)gridDim.x * blockDim.x;
    for (size_t i = idx; i < NX4 + NW4; i += stride) {
        bool isx = (i < NX4);
        size_t j = isx ? i : (i - NX4);
        float4 v = isx ? ((const float4*)X)[j] : ((const float4*)W)[j];
        v.x = wmma::__float_to_tf32(v.x);
        v.y = wmma::__float_to_tf32(v.y);
        v.z = wmma::__float_to_tf32(v.z);
        v.w = wmma::__float_to_tf32(v.w);
        if (isx) ((float4*)g_xt)[j] = v;
        else     ((float4*)g_wt)[j] = v;
    }
}

// ===========================================================================
// Phase 1: single-pass tf32 GEMM: xg[16384,4096] = xt[16384,1024] @ wt[4096,1024]^T
// Block tile 128x128, BK=32 fp32, double-buffered cp.async.
// 8 warps (2M x 4N), warp tile 64x32, m16n16k8 tf32 fragments, fp32 accum.
// Inputs pre-rounded: zero in-loop conversion.
// ===========================================================================
#define BM 128
#define BN 128
#define BK 32
#define BKS 36   // padded leading dim in floats (144B, mult of 16B)

__global__ __launch_bounds__(256)
void gemm_tf32_kernel()
{
    extern __shared__ float smf[];
    float* As = smf;                  // [2][BM][BKS]
    float* Bs = smf + 2 * BM * BKS;   // [2][BN][BKS]

    const int tid = threadIdx.x;
    const int m0 = blockIdx.y * BM;
    const int n0 = blockIdx.x * BN;

    const int warp = tid >> 5;
    const int wm = warp >> 2;   // 0..1 (M dir, 64 rows)
    const int wn = warp & 3;    // 0..3 (N dir, 32 cols)

    wmma::fragment<wmma::accumulator, 16, 16, 8, float> acc[4][2];
#pragma unroll
    for (int i = 0; i < 4; i++)
#pragma unroll
        for (int j = 0; j < 2; j++) wmma::fill_fragment(acc[i][j], 0.0f);

    const float* __restrict__ Ap = g_xt;
    const float* __restrict__ Bp = g_wt;

    // 2048 cp16 per stage (A 1024 + B 1024), 8 per thread
    auto load_stage = [&](int s, int kt) {
        float* ab = As + s * BM * BKS;
        float* bb = Bs + s * BN * BKS;
#pragma unroll
        for (int q = 0; q < 8; q++) {
            int i = tid + q * 256;            // 0..2047
            int r = (i & 1023) >> 3;          // row 0..127
            int c = i & 7;                    // float4 within 32-float row
            if (i < 1024)
                cp16(ab + r * BKS + c * 4, Ap + (size_t)(m0 + r) * IDIM + kt * BK + c * 4);
            else
                cp16(bb + r * BKS + c * 4, Bp + (size_t)(n0 + r) * HDIM + kt * BK + c * 4);
        }
        cp_commit();
    };

    load_stage(0, 0);
    load_stage(1, 1);

    const int KT = IDIM / BK;  // 32
    for (int kt = 0; kt < KT; ++kt) {
        const int s = kt & 1;
        if (kt + 2 < KT) cp_wait<1>(); else cp_wait<0>();
        __syncthreads();

        const float* Ab = As + s * BM * BKS + wm * 64 * BKS;
        const float* Bb = Bs + s * BN * BKS + wn * 32 * BKS;
#pragma unroll
        for (int kk = 0; kk < BK; kk += 8) {
            wmma::fragment<wmma::matrix_a, 16, 16, 8, wmma::precision::tf32, wmma::row_major> af[4];
            wmma::fragment<wmma::matrix_b, 16, 16, 8, wmma::precision::tf32, wmma::col_major> bf[2];
#pragma unroll
            for (int i = 0; i < 4; i++)
                wmma::load_matrix_sync(af[i], Ab + i * 16 * BKS + kk, BKS);
#pragma unroll
            for (int j = 0; j < 2; j++)
                wmma::load_matrix_sync(bf[j], Bb + j * 16 * BKS + kk, BKS);
#pragma unroll
            for (int i = 0; i < 4; i++)
#pragma unroll
                for (int j = 0; j < 2; j++)
                    wmma::mma_sync(acc[i][j], af[i], bf[j], acc[i][j]);
        }
        __syncthreads();

        if (kt + 2 < KT) load_stage(s, kt + 2);
    }

#pragma unroll
    for (int i = 0; i < 4; i++)
#pragma unroll
        for (int j = 0; j < 2; j++) {
            size_t row = (size_t)(m0 + wm * 64 + i * 16);
            size_t col = (size_t)(n0 + wn * 32 + j * 16);
            wmma::store_matrix_sync(&g_xg[row * G4 + col], acc[i][j], G4, wmma::mem_row_major);
        }
}

// ===========================================================================
// Phase 2: persistent recurrence, all-warps-active bf16 3-term mma
// (structure from R7, with one sync per chunk instead of two: chunk loads
// are issued AFTER the head __syncthreads, so the tail sync is not needed).
// ===========================================================================
#define RBLK 128
#define RTHREADS 256
#define UROWS 32
#define ULD  1040            // 1024 + 16 pad (bf16 elems)
#define HC   256             // K-chunk size
#define HCLD 264             // padded chunk row (bf16 elems)
#define CPLD 36

#define U_ELEMS   (UROWS * ULD)               // 33280
#define HPLANE    (BATCH * HCLD)              // 8448
#define HBUF      (2 * HPLANE)                // 16896
#define SM_ELEMS  (2 * U_ELEMS + 2 * HBUF)    // 100352 bf16 = 200704 B

__global__ __launch_bounds__(256)
void lstm_rec_kernel(const float* __restrict__ Uw,
                     const float* __restrict__ b_ih,
                     const float* __restrict__ b_hh,
                     float* __restrict__ out)
{
    extern __shared__ __nv_bfloat16 smr[];
    __nv_bfloat16* Uhi = smr;
    __nv_bfloat16* Ulo = smr + U_ELEMS;
    __nv_bfloat16* Hb[2] = { smr + 2 * U_ELEMS, smr + 2 * U_ELEMS + HBUF };
    float* Cp = (float*)(smr + 2 * U_ELEMS);   // union with h buffers (step-end only)

    const int tid   = threadIdx.x;
    const int warp  = tid >> 5;
    const int bcol0 = blockIdx.x * 8;

    // ---- Load U slice -> smem bf16 hi/lo ----
    for (int i = tid; i < UROWS * (IDIM / 4); i += RTHREADS) {
        int n  = i >> 8;
        int c4 = i & 255;
        int grow = (n >> 3) * HDIM + bcol0 + (n & 7);
        float4 v = *(const float4*)(Uw + (size_t)grow * HDIM + c4 * 4);
        __nv_bfloat16 h0 = __float2bfloat16(v.x), h1 = __float2bfloat16(v.y);
        __nv_bfloat16 h2 = __float2bfloat16(v.z), h3 = __float2bfloat16(v.w);
        __nv_bfloat16 l0 = __float2bfloat16(v.x - __bfloat162float(h0));
        __nv_bfloat16 l1 = __float2bfloat16(v.y - __bfloat162float(h1));
        __nv_bfloat16 l2 = __float2bfloat16(v.z - __bfloat162float(h2));
        __nv_bfloat16 l3 = __float2bfloat16(v.w - __bfloat162float(h3));
        ushort hv[4] = { *(ushort*)&h0, *(ushort*)&h1, *(ushort*)&h2, *(ushort*)&h3 };
        ushort lv[4] = { *(ushort*)&l0, *(ushort*)&l1, *(ushort*)&l2, *(ushort*)&l3 };
        *(uint2*)&Uhi[n * ULD + c4 * 4] = *(uint2*)hv;
        *(uint2*)&Ulo[n * ULD + c4 * 4] = *(uint2*)lv;
    }

    const int b   = tid >> 3;
    const int jj  = tid & 7;
    const int col = bcol0 + jj;

    float bsum[4];
#pragma unroll
    for (int g = 0; g < 4; g++) bsum[g] = b_ih[g * HDIM + col] + b_hh[g * HDIM + col];

    float c_state = 0.0f;
    float* hn_out = out + (size_t)T_STEPS * BATCH * HDIM;
    float* cn_out = hn_out + BATCH * HDIM;

    __syncthreads();

    auto load_chunk = [&](int s, int ch) {
        __nv_bfloat16* hb = Hb[s];
#pragma unroll
        for (int q = 0; q < 8; q++) {
            int idx = tid + q * RTHREADS;   // 0..2047
            int plane = idx >> 10;          // 0 hi, 1 lo
            int rem = idx & 1023;
            int row = rem >> 5;             // 0..31
            int c   = rem & 31;             // 16B unit (8 bf16)
            cp16(hb + plane * HPLANE + row * HCLD + c * 8,
                 &g_hx[plane][row * HDIM + ch * HC + c * 8]);
        }
        cp_commit();
    };

    for (int t = 0; t < T_STEPS; ++t) {
        const float* xgp = g_xg + ((size_t)(t * BATCH + b)) * G4 + col;
        float xv[4];
#pragma unroll
        for (int g = 0; g < 4; g++) xv[g] = __ldg(xgp + g * HDIM);

        float gv[4];
#pragma unroll
        for (int g = 0; g < 4; g++) gv[g] = xv[g] + bsum[g];

        if (t > 0) {
            load_chunk(0, 0);

            wmma::fragment<wmma::accumulator, 16, 16, 16, float> acc[2][2];
#pragma unroll
            for (int i = 0; i < 2; i++)
#pragma unroll
                for (int j = 0; j < 2; j++) wmma::fill_fragment(acc[i][j], 0.0f);

#pragma unroll
            for (int ch = 0; ch < 4; ++ch) {
                cp_wait<0>();          // chunk ch resident
                __syncthreads();       // also: all warps done reading buf (ch+1)&1
                if (ch < 3) load_chunk((ch + 1) & 1, ch + 1);   // safe: overwrites buf read at ch-1

                const __nv_bfloat16* hb = Hb[ch & 1];
#pragma unroll
                for (int s = 0; s < 6; ++s) {
                    int kc   = warp * 96 + s * 16;      // 0..767 concat-K
                    int term = kc >> 8;                 // 0:hi*Uhi 1:hi*Ulo 2:lo*Uhi
                    int koff = kc & 255;
                    const __nv_bfloat16* ab = hb + (term == 2 ? HPLANE : 0) + koff;
                    const __nv_bfloat16* bb = (term == 1 ? Ulo : Uhi) + ch * HC + koff;

                    wmma::fragment<wmma::matrix_a, 16, 16, 16, __nv_bfloat16, wmma::row_major> af[2];
                    wmma::fragment<wmma::matrix_b, 16, 16, 16, __nv_bfloat16, wmma::col_major> bf[2];
                    wmma::load_matrix_sync(af[0], ab, HCLD);
                    wmma::load_matrix_sync(af[1], ab + 16 * HCLD, HCLD);
                    wmma::load_matrix_sync(bf[0], bb, ULD);
                    wmma::load_matrix_sync(bf[1], bb + 16 * ULD, ULD);
#pragma unroll
                    for (int i = 0; i < 2; i++)
#pragma unroll
                        for (int j = 0; j < 2; j++)
                            wmma::mma_sync(acc[i][j], af[i], bf[j], acc[i][j]);
                }
            }

            __syncthreads();   // all warps done reading Hb before Cp overwrite (Cp spans both bufs)

            float* cpw = Cp + warp * (BATCH * CPLD);
#pragma unroll
            for (int i = 0; i < 2; i++)
#pragma unroll
                for (int j = 0; j < 2; j++)
                    wmma::store_matrix_sync(cpw + i * 16 * CPLD + j * 16,
                                            acc[i][j], CPLD, wmma::mem_row_major);
            __syncthreads();

#pragma unroll
            for (int w = 0; w < 8; ++w) {
                const float* cr = Cp + w * (BATCH * CPLD) + b * CPLD + jj;
                gv[0] += cr[0];
                gv[1] += cr[8];
                gv[2] += cr[16];
                gv[3] += cr[24];
            }
        }

        float it = 1.0f / (1.0f + expf(-gv[0]));
        float ft = 1.0f / (1.0f + expf(-gv[1]));
        float ct = tanhf(gv[2]);
        float ot = 1.0f / (1.0f + expf(-gv[3]));
        c_state = ft * c_state + it * ct;
        float h = ot * tanhf(c_state);

        out[(size_t)t * BATCH * HDIM + b * HDIM + col] = h;
        __nv_bfloat16 hhi = __float2bfloat16(h);
        __nv_bfloat16 hlo = __float2bfloat16(h - __bfloat162float(hhi));
        g_hx[0][b * HDIM + col] = hhi;
        g_hx[1][b * HDIM + col] = hlo;

        if (t == T_STEPS - 1) {
            hn_out[b * HDIM + col] = h;
            cn_out[b * HDIM + col] = c_state;
        }

        // ---- grid barrier ----
        __syncthreads();
        if (tid == 0) {
            __threadfence();
            atomicAdd(&g_bar, 1u);
            const unsigned target = (unsigned)(t + 1) * RBLK;
            volatile unsigned* p = &g_bar;
            while (*p < target) { }
            __threadfence();
        }
        __syncthreads();
    }
}

__global__ void reset_bar_kernel() { g_bar = 0u; }

// ===========================================================================
// Launch
// ===========================================================================
extern "C" void kernel_launch(void* const* d_in, const int* in_sizes, int n_in,
                              void* d_out, int out_size)
{
    (void)in_sizes; (void)n_in; (void)out_size;
    const float* x  = (const float*)d_in[0];
    const float* W  = (const float*)d_in[1];
    const float* U  = (const float*)d_in[2];
    const float* bi = (const float*)d_in[3];
    const float* bh = (const float*)d_in[4];
    float* out = (float*)d_out;

    const int gemm_smem = 2 * (BM * BKS + BN * BKS) * (int)sizeof(float);   // 73728
    const int rec_smem  = SM_ELEMS * (int)sizeof(__nv_bfloat16);            // 200704

    cudaFuncSetAttribute(gemm_tf32_kernel, cudaFuncAttributeMaxDynamicSharedMemorySize, gemm_smem);
    cudaFuncSetAttribute(lstm_rec_kernel, cudaFuncAttributeMaxDynamicSharedMemorySize, rec_smem);

    round_kernel<<<8192, 256>>>(x, W);
    gemm_tf32_kernel<<<dim3(G4 / BN, M_TOT / BM), 256, gemm_smem>>>();
    reset_bar_kernel<<<1, 1>>>();
    lstm_rec_kernel<<<RBLK, RTHREADS, rec_smem>>>(U, bi, bh, out);
}

// round 14
// speedup vs baseline: 1.1644x; 1.1644x over previous
#include <cuda_runtime.h>
#include <cuda_bf16.h>
#include <mma.h>
#include <math.h>
#include <stdint.h>

using namespace nvcuda;

// Problem constants
#define T_STEPS 512
#define BATCH   32
#define IDIM    1024
#define HDIM    1024
#define G4      4096                  // 4*H
#define M_TOT   (T_STEPS * BATCH)     // 16384
#define GK      3072                  // extended K for 3-term bf16 split

// ---------------------------------------------------------------------------
// Scratch (static __device__ — no allocation at kernel_launch time)
// ---------------------------------------------------------------------------
__device__ float          g_xg[(size_t)M_TOT * G4];   // 256 MB: precomputed x@W^T
__device__ __nv_bfloat16  g_A[(size_t)M_TOT * GK];    // 96 MB: [x_hi | x_hi | x_lo]
__device__ __nv_bfloat16  g_B[(size_t)G4 * GK];       // 24 MB: [W_hi | W_lo | W_hi]
__device__ __nv_bfloat16  g_hx[2][BATCH * HDIM];      // h exchange: [hi|lo] planes
__device__ unsigned       g_bar;                       // grid barrier counter

// ---------------------------------------------------------------------------
// cp.async helpers
// ---------------------------------------------------------------------------
__device__ __forceinline__ void cp16(void* dst, const void* src) {
    unsigned d = (unsigned)__cvta_generic_to_shared(dst);
    asm volatile("cp.async.cg.shared.global [%0], [%1], 16;\n" :: "r"(d), "l"(src));
}
__device__ __forceinline__ void cp_commit() { asm volatile("cp.async.commit_group;\n"); }
template <int N>
__device__ __forceinline__ void cp_wait() { asm volatile("cp.async.wait_group %0;\n" :: "n"(N)); }

// ===========================================================================
// Split kernel: build A' = [x_hi | x_hi | x_lo], B' = [W_hi | W_lo | W_hi]
// ===========================================================================
__global__ __launch_bounds__(256)
void split_kernel(const float* __restrict__ X, const float* __restrict__ W)
{
    const size_t NX4 = (size_t)M_TOT * IDIM / 4;   // 4,194,304
    const size_t NW4 = (size_t)G4 * HDIM / 4;      // 1,048,576
    size_t idx = (size_t)blockIdx.x * blockDim.x + threadIdx.x;
    size_t stride = (size_t)gridDim.x * blockDim.x;
    for (size_t i = idx; i < NX4 + NW4; i += stride) {
        bool isx = (i < NX4);
        size_t j = isx ? i : (i - NX4);
        size_t row = j >> 8;          // /256 (1024/4)
        size_t c4  = j & 255;
        const float4 v = isx ? ((const float4*)X)[j] : ((const float4*)W)[j];
        __nv_bfloat16 h0 = __float2bfloat16(v.x), h1 = __float2bfloat16(v.y);
        __nv_bfloat16 h2 = __float2bfloat16(v.z), h3 = __float2bfloat16(v.w);
        __nv_bfloat16 l0 = __float2bfloat16(v.x - __bfloat162float(h0));
        __nv_bfloat16 l1 = __float2bfloat16(v.y - __bfloat162float(h1));
        __nv_bfloat16 l2 = __float2bfloat16(v.z - __bfloat162float(h2));
        __nv_bfloat16 l3 = __float2bfloat16(v.w - __bfloat162float(h3));
        ushort hs[4] = { *(ushort*)&h0, *(ushort*)&h1, *(ushort*)&h2, *(ushort*)&h3 };
        ushort ls[4] = { *(ushort*)&l0, *(ushort*)&l1, *(ushort*)&l2, *(ushort*)&l3 };
        uint2 hv = { (uint32_t)hs[0] | ((uint32_t)hs[1] << 16),
                     (uint32_t)hs[2] | ((uint32_t)hs[3] << 16) };
        uint2 lv = { (uint32_t)ls[0] | ((uint32_t)ls[1] << 16),
                     (uint32_t)ls[2] | ((uint32_t)ls[3] << 16) };
        size_t base = row * GK + c4 * 4;
        if (isx) {
            *(uint2*)&g_A[base]           = hv;
            *(uint2*)&g_A[base + IDIM]    = hv;
            *(uint2*)&g_A[base + 2*IDIM]  = lv;
        } else {
            *(uint2*)&g_B[base]           = hv;
            *(uint2*)&g_B[base + HDIM]    = lv;
            *(uint2*)&g_B[base + 2*HDIM]  = hv;
        }
    }
}

// ===========================================================================
// Phase 1: wmma bf16 GEMM: xg[16384,4096] = A'[16384,3072] @ B'[4096,3072]^T
// Block tile 128(M) x 256(N), BK=64, double-buffered cp.async.
// 8 warps (2M x 4N), warp tile 64x64: 8 fragment loads per 16 HMMAs
// (2x better mma/LDSM ratio than R6's 64x32 tile).
// ===========================================================================
#define BM 128
#define BN 256
#define BK 64
#define BKS 72   // padded leading dim in bf16 elements (144B, mult of 16B)

__global__ __launch_bounds__(256)
void gemm_bf16_kernel()
{
    extern __shared__ __nv_bfloat16 smb[];
    __nv_bfloat16* As = smb;                  // [2][BM][BKS]
    __nv_bfloat16* Bs = smb + 2 * BM * BKS;   // [2][BN][BKS]

    const int tid = threadIdx.x;
    const int m0 = blockIdx.y * BM;
    const int n0 = blockIdx.x * BN;

    const int warp = tid >> 5;
    const int wm = warp >> 2;   // 0..1 (M dir, 64 rows)
    const int wn = warp & 3;    // 0..3 (N dir, 64 cols)

    wmma::fragment<wmma::accumulator, 16, 16, 16, float> acc[4][4];
#pragma unroll
    for (int i = 0; i < 4; i++)
#pragma unroll
        for (int j = 0; j < 4; j++) wmma::fill_fragment(acc[i][j], 0.0f);

    const __nv_bfloat16* __restrict__ Ap = g_A;
    const __nv_bfloat16* __restrict__ Bp = g_B;

    // 3072 cp16 per stage (A 1024 + B 2048), 12 per thread
    auto load_stage = [&](int s, int kt) {
        __nv_bfloat16* ab = As + s * BM * BKS;
        __nv_bfloat16* bb = Bs + s * BN * BKS;
#pragma unroll
        for (int q = 0; q < 12; q++) {
            int i = tid + q * 256;            // 0..3071
            if (i < 1024) {
                int r = i >> 3, c = i & 7;
                cp16(ab + r * BKS + c * 8, Ap + (size_t)(m0 + r) * GK + kt * BK + c * 8);
            } else {
                int j = i - 1024;
                int r = j >> 3, c = j & 7;
                cp16(bb + r * BKS + c * 8, Bp + (size_t)(n0 + r) * GK + kt * BK + c * 8);
            }
        }
        cp_commit();
    };

    load_stage(0, 0);
    load_stage(1, 1);

    const int KT = GK / BK;  // 48
    for (int kt = 0; kt < KT; ++kt) {
        const int s = kt & 1;
        if (kt + 2 < KT) cp_wait<1>(); else cp_wait<0>();
        __syncthreads();

        const __nv_bfloat16* Ab = As + s * BM * BKS + wm * 64 * BKS;
        const __nv_bfloat16* Bb = Bs + s * BN * BKS + wn * 64 * BKS;
#pragma unroll
        for (int kk = 0; kk < BK; kk += 16) {
            wmma::fragment<wmma::matrix_a, 16, 16, 16, __nv_bfloat16, wmma::row_major> af[4];
            wmma::fragment<wmma::matrix_b, 16, 16, 16, __nv_bfloat16, wmma::col_major> bf[4];
#pragma unroll
            for (int i = 0; i < 4; i++)
                wmma::load_matrix_sync(af[i], Ab + i * 16 * BKS + kk, BKS);
#pragma unroll
            for (int j = 0; j < 4; j++)
                wmma::load_matrix_sync(bf[j], Bb + j * 16 * BKS + kk, BKS);
#pragma unroll
            for (int i = 0; i < 4; i++)
#pragma unroll
                for (int j = 0; j < 4; j++)
                    wmma::mma_sync(acc[i][j], af[i], bf[j], acc[i][j]);
        }
        __syncthreads();

        if (kt + 2 < KT) load_stage(s, kt + 2);
    }

#pragma unroll
    for (int i = 0; i < 4; i++)
#pragma unroll
        for (int j = 0; j < 4; j++) {
            size_t row = (size_t)(m0 + wm * 64 + i * 16);
            size_t col = (size_t)(n0 + wn * 64 + j * 16);
            wmma::store_matrix_sync(&g_xg[row * G4 + col], acc[i][j], G4, wmma::mem_row_major);
        }
}

// ===========================================================================
// Phase 2: persistent recurrence, all-warps-active bf16 3-term mma
// (one sync per chunk) + next-step xg prefetch issued BEFORE the grid
// barrier so the DRAM latency hides under the barrier wait.
// ===========================================================================
#define RBLK 128
#define RTHREADS 256
#define UROWS 32
#define ULD  1040            // 1024 + 16 pad (bf16 elems)
#define HC   256             // K-chunk size
#define HCLD 264             // padded chunk row (bf16 elems)
#define CPLD 36

#define U_ELEMS   (UROWS * ULD)               // 33280
#define HPLANE    (BATCH * HCLD)              // 8448
#define HBUF      (2 * HPLANE)                // 16896
#define SM_ELEMS  (2 * U_ELEMS + 2 * HBUF)    // 100352 bf16 = 200704 B

__global__ __launch_bounds__(256)
void lstm_rec_kernel(const float* __restrict__ Uw,
                     const float* __restrict__ b_ih,
                     const float* __restrict__ b_hh,
                     float* __restrict__ out)
{
    extern __shared__ __nv_bfloat16 smr[];
    __nv_bfloat16* Uhi = smr;
    __nv_bfloat16* Ulo = smr + U_ELEMS;
    __nv_bfloat16* Hb[2] = { smr + 2 * U_ELEMS, smr + 2 * U_ELEMS + HBUF };
    float* Cp = (float*)(smr + 2 * U_ELEMS);   // union with h buffers (step-end only)

    const int tid   = threadIdx.x;
    const int warp  = tid >> 5;
    const int bcol0 = blockIdx.x * 8;

    // ---- Load U slice -> smem bf16 hi/lo ----
    for (int i = tid; i < UROWS * (IDIM / 4); i += RTHREADS) {
        int n  = i >> 8;
        int c4 = i & 255;
        int grow = (n >> 3) * HDIM + bcol0 + (n & 7);
        float4 v = *(const float4*)(Uw + (size_t)grow * HDIM + c4 * 4);
        __nv_bfloat16 h0 = __float2bfloat16(v.x), h1 = __float2bfloat16(v.y);
        __nv_bfloat16 h2 = __float2bfloat16(v.z), h3 = __float2bfloat16(v.w);
        __nv_bfloat16 l0 = __float2bfloat16(v.x - __bfloat162float(h0));
        __nv_bfloat16 l1 = __float2bfloat16(v.y - __bfloat162float(h1));
        __nv_bfloat16 l2 = __float2bfloat16(v.z - __bfloat162float(h2));
        __nv_bfloat16 l3 = __float2bfloat16(v.w - __bfloat162float(h3));
        ushort hv[4] = { *(ushort*)&h0, *(ushort*)&h1, *(ushort*)&h2, *(ushort*)&h3 };
        ushort lv[4] = { *(ushort*)&l0, *(ushort*)&l1, *(ushort*)&l2, *(ushort*)&l3 };
        *(uint2*)&Uhi[n * ULD + c4 * 4] = *(uint2*)hv;
        *(uint2*)&Ulo[n * ULD + c4 * 4] = *(uint2*)lv;
    }

    const int b   = tid >> 3;
    const int jj  = tid & 7;
    const int col = bcol0 + jj;

    float bsum[4];
#pragma unroll
    for (int g = 0; g < 4; g++) bsum[g] = b_ih[g * HDIM + col] + b_hh[g * HDIM + col];

    float c_state = 0.0f;
    float* hn_out = out + (size_t)T_STEPS * BATCH * HDIM;
    float* cn_out = hn_out + BATCH * HDIM;

    __syncthreads();

    auto load_chunk = [&](int s, int ch) {
        __nv_bfloat16* hb = Hb[s];
#pragma unroll
        for (int q = 0; q < 8; q++) {
            int idx = tid + q * RTHREADS;   // 0..2047
            int plane = idx >> 10;          // 0 hi, 1 lo
            int rem = idx & 1023;
            int row = rem >> 5;             // 0..31
            int c   = rem & 31;             // 16B unit (8 bf16)
            cp16(hb + plane * HPLANE + row * HCLD + c * 8,
                 &g_hx[plane][row * HDIM + ch * HC + c * 8]);
        }
        cp_commit();
    };

    // prefetch xg for t=0
    float xv[4];
#pragma unroll
    for (int g = 0; g < 4; g++)
        xv[g] = __ldg(g_xg + (size_t)b * G4 + g * HDIM + col);

    for (int t = 0; t < T_STEPS; ++t) {
        float gv[4];
#pragma unroll
        for (int g = 0; g < 4; g++) gv[g] = xv[g] + bsum[g];

        if (t > 0) {
            load_chunk(0, 0);

            wmma::fragment<wmma::accumulator, 16, 16, 16, float> acc[2][2];
#pragma unroll
            for (int i = 0; i < 2; i++)
#pragma unroll
                for (int j = 0; j < 2; j++) wmma::fill_fragment(acc[i][j], 0.0f);

#pragma unroll
            for (int ch = 0; ch < 4; ++ch) {
                cp_wait<0>();          // chunk ch resident
                __syncthreads();       // all warps done reading buf (ch+1)&1
                if (ch < 3) load_chunk((ch + 1) & 1, ch + 1);

                const __nv_bfloat16* hb = Hb[ch & 1];
#pragma unroll
                for (int s = 0; s < 6; ++s) {
                    int kc   = warp * 96 + s * 16;      // 0..767 concat-K
                    int term = kc >> 8;                 // 0:hi*Uhi 1:hi*Ulo 2:lo*Uhi
                    int koff = kc & 255;
                    const __nv_bfloat16* ab = hb + (term == 2 ? HPLANE : 0) + koff;
                    const __nv_bfloat16* bb = (term == 1 ? Ulo : Uhi) + ch * HC + koff;

                    wmma::fragment<wmma::matrix_a, 16, 16, 16, __nv_bfloat16, wmma::row_major> af[2];
                    wmma::fragment<wmma::matrix_b, 16, 16, 16, __nv_bfloat16, wmma::col_major> bf[2];
                    wmma::load_matrix_sync(af[0], ab, HCLD);
                    wmma::load_matrix_sync(af[1], ab + 16 * HCLD, HCLD);
                    wmma::load_matrix_sync(bf[0], bb, ULD);
                    wmma::load_matrix_sync(bf[1], bb + 16 * ULD, ULD);
#pragma unroll
                    for (int i = 0; i < 2; i++)
#pragma unroll
                        for (int j = 0; j < 2; j++)
                            wmma::mma_sync(acc[i][j], af[i], bf[j], acc[i][j]);
                }
            }

            __syncthreads();   // Hb reads done before Cp overwrite

            float* cpw = Cp + warp * (BATCH * CPLD);
#pragma unroll
            for (int i = 0; i < 2; i++)
#pragma unroll
                for (int j = 0; j < 2; j++)
                    wmma::store_matrix_sync(cpw + i * 16 * CPLD + j * 16,
                                            acc[i][j], CPLD, wmma::mem_row_major);
            __syncthreads();

#pragma unroll
            for (int w = 0; w < 8; ++w) {
                const float* cr = Cp + w * (BATCH * CPLD) + b * CPLD + jj;
                gv[0] += cr[0];
                gv[1] += cr[8];
                gv[2] += cr[16];
                gv[3] += cr[24];
            }
        }

        float it = 1.0f / (1.0f + expf(-gv[0]));
        float ft = 1.0f / (1.0f + expf(-gv[1]));
        float ct = tanhf(gv[2]);
        float ot = 1.0f / (1.0f + expf(-gv[3]));
        c_state = ft * c_state + it * ct;
        float h = ot * tanhf(c_state);

        out[(size_t)t * BATCH * HDIM + b * HDIM + col] = h;
        __nv_bfloat16 hhi = __float2bfloat16(h);
        __nv_bfloat16 hlo = __float2bfloat16(h - __bfloat162float(hhi));
        g_hx[0][b * HDIM + col] = hhi;
        g_hx[1][b * HDIM + col] = hlo;

        if (t == T_STEPS - 1) {
            hn_out[b * HDIM + col] = h;
            cn_out[b * HDIM + col] = c_state;
        }

        // prefetch next step's xg BEFORE the barrier — latency hides in the wait
        float xn[4] = {0.f, 0.f, 0.f, 0.f};
        if (t + 1 < T_STEPS) {
            const float* xgp = g_xg + ((size_t)((t + 1) * BATCH + b)) * G4 + col;
#pragma unroll
            for (int g = 0; g < 4; g++) xn[g] = __ldg(xgp + g * HDIM);
        }

        // ---- grid barrier ----
        __syncthreads();
        if (tid == 0) {
            __threadfence();
            atomicAdd(&g_bar, 1u);
            const unsigned target = (unsigned)(t + 1) * RBLK;
            volatile unsigned* p = &g_bar;
            while (*p < target) { }
            __threadfence();
        }
        __syncthreads();

#pragma unroll
        for (int g = 0; g < 4; g++) xv[g] = xn[g];
    }
}

__global__ void reset_bar_kernel() { g_bar = 0u; }

// ===========================================================================
// Launch
// ===========================================================================
extern "C" void kernel_launch(void* const* d_in, const int* in_sizes, int n_in,
                              void* d_out, int out_size)
{
    (void)in_sizes; (void)n_in; (void)out_size;
    const float* x  = (const float*)d_in[0];
    const float* W  = (const float*)d_in[1];
    const float* U  = (const float*)d_in[2];
    const float* bi = (const float*)d_in[3];
    const float* bh = (const float*)d_in[4];
    float* out = (float*)d_out;

    const int gemm_smem = 2 * (BM * BKS + BN * BKS) * (int)sizeof(__nv_bfloat16);  // 110592
    const int rec_smem  = SM_ELEMS * (int)sizeof(__nv_bfloat16);                   // 200704

    cudaFuncSetAttribute(gemm_bf16_kernel, cudaFuncAttributeMaxDynamicSharedMemorySize, gemm_smem);
    cudaFuncSetAttribute(lstm_rec_kernel, cudaFuncAttributeMaxDynamicSharedMemorySize, rec_smem);

    split_kernel<<<8192, 256>>>(x, W);
    gemm_bf16_kernel<<<dim3(G4 / BN, M_TOT / BM), 256, gemm_smem>>>();
    reset_bar_kernel<<<1, 1>>>();
    lstm_rec_kernel<<<RBLK, RTHREADS, rec_smem>>>(U, bi, bh, out);
}